// round 11
// baseline (speedup 1.0000x reference)
#include <cuda_runtime.h>
#include <cstdint>

#define B_   8
#define LQ_  2048
#define LK_  2048
#define D_   1024
#define DV_  1024

// ---------------- tiled scratch (device globals) ----------------
// Tiled arrays: sequence of 32KB tiles [128 rows x 32 cols x (hi,lo) pair].
// Element (r,c) pair at float offset 2*(r*32 + (c ^ ((r&7)<<2))).
__device__ float g_qT [(long)2 * B_ * LQ_ * D_];
__device__ float g_kT [(long)2 * B_ * LK_ * D_];
__device__ float g_WtT[(long)2 * D_ * D_];
__device__ float g_vTT[(long)2 * B_ * DV_ * LK_];
__device__ float g_qWT[(long)2 * B_ * LQ_ * D_];
__device__ float g_wT [(long)2 * B_ * LQ_ * LK_];

// ---------------- helpers ----------------
__device__ __forceinline__ uint32_t smem_u32(const void* p) {
    uint32_t a;
    asm("{ .reg .u64 t; cvta.to.shared.u64 t, %1; cvt.u32.u64 %0, t; }" : "=r"(a) : "l"(p));
    return a;
}

__device__ __forceinline__ uint32_t f2tf32(float x) {
    uint32_t u;
    asm("cvt.rna.tf32.f32 %0, %1;" : "=r"(u) : "f"(x));
    return u;
}

// split fp32 -> (tf32 hi, fp32 lo); lo is fed raw to the MMA (HMMA truncates it;
// lo has <=12 significant bits so the truncation residual is ~2^-24 relative).
__device__ __forceinline__ float2 splitpair(float x) {
    float h = __uint_as_float(f2tf32(x));
    return make_float2(h, x - h);
}

__device__ __forceinline__ void mma_tf32(float* d, const uint32_t* a, const uint32_t* b) {
    asm volatile(
        "mma.sync.aligned.m16n8k8.row.col.f32.tf32.tf32.f32 "
        "{%0,%1,%2,%3}, {%4,%5,%6,%7}, {%8,%9}, {%0,%1,%2,%3};"
        : "+f"(d[0]), "+f"(d[1]), "+f"(d[2]), "+f"(d[3])
        : "r"(a[0]), "r"(a[1]), "r"(a[2]), "r"(a[3]),
          "r"(b[0]), "r"(b[1]));
}

__device__ __forceinline__ void bulk_cp(uint32_t dst, const void* src,
                                        uint32_t bytes, uint32_t mbar) {
    asm volatile("cp.async.bulk.shared::cluster.global.mbarrier::complete_tx::bytes "
                 "[%0], [%1], %2, [%3];"
                 :: "r"(dst), "l"(src), "r"(bytes), "r"(mbar) : "memory");
}

#define MBARRIER_INIT(m, c) \
    asm volatile("mbarrier.init.shared.b64 [%0], %1;" :: "r"(m), "r"(c) : "memory")
#define MBARRIER_EXPECT_TX(m, b) \
    asm volatile("mbarrier.arrive.expect_tx.shared.b64 _, [%0], %1;" :: "r"(m), "r"(b) : "memory")

#define MBARRIER_WAIT_PARITY(mbar_smem_addr, phase_parity) do { \
    uint32_t _mbar = (uint32_t)(mbar_smem_addr); \
    uint32_t _parity = (uint32_t)(phase_parity); \
    uint32_t _done; \
    asm volatile( \
        "{\n\t.reg .pred p;\n\t" \
        "mbarrier.try_wait.parity.acquire.cta.shared::cta.b64 p, [%1], %2;\n\t" \
        "selp.b32 %0, 1, 0, p;\n\t}" \
        : "=r"(_done) : "r"(_mbar), "r"(_parity) : "memory"); \
    if (!_done) { \
        asm volatile( \
            "{\n\t.reg .pred P1;\n\t" \
            "WAIT_LOOP_%=:\n\t" \
            "mbarrier.try_wait.parity.acquire.cta.shared::cta.b64 P1, [%0], %1, 0x989680;\n\t" \
            "@P1 bra.uni WAIT_DONE_%=;\n\t" \
            "bra.uni WAIT_LOOP_%=;\n\t" \
            "WAIT_DONE_%=:\n\t}" \
            :: "r"(_mbar), "r"(_parity) : "memory"); \
    } \
} while (0)

// ---------------- GEMM config ----------------
#define STAGES 3
#define TILE_FLOATS 8192                 // 128 x 32 x 2 (hi,lo)
#define TILE_BYTES  32768
#define STAGE_BYTES (2 * TILE_BYTES)     // A tile + B tile
#define SMEM_BASE   1024
#define GEMM_SMEM   (SMEM_BASE + STAGES * STAGE_BYTES)   // 197632

// C[M,N] = A[M,K] @ Bt[N,K]^T; A, Bt are pre-split TILED arrays (above).
// TILED_C: write C pre-split tiled (to feed the next GEMM); else row-major fp32.
template<bool TILED_C>
__global__ __launch_bounds__(256, 1) void gemm3x_tf32(
    const float* __restrict__ A, const float* __restrict__ Bt, float* __restrict__ C,
    int M, int N, int K, long sA, long sB, long sC)
{
    extern __shared__ float sf[];
    const uint32_t sbase = smem_u32(sf);

    A  += (long)blockIdx.z * sA;
    Bt += (long)blockIdx.z * sB;
    C  += (long)blockIdx.z * sC;

    const int tid  = threadIdx.x;
    const int lane = tid & 31;
    const int warp = tid >> 5;
    const int g    = lane >> 2;          // 0..7
    const int t    = lane & 3;           // 0..3
    const int sw   = g << 2;
    const int wm   = (warp >> 2) * 64;
    const int wn   = (warp & 3) * 32;
    const int Kb   = K >> 5;

    if (tid == 0) {
        #pragma unroll
        for (int s = 0; s < STAGES; s++) MBARRIER_INIT(sbase + 8 * s, 1);
    }
    __syncthreads();

    auto fill = [&](int it2) {
        if (tid == 0) {
            const int buf = it2 % STAGES;
            const uint32_t mbar = sbase + 8 * buf;
            const uint32_t st   = sbase + SMEM_BASE + buf * STAGE_BYTES;
            MBARRIER_EXPECT_TX(mbar, STAGE_BYTES);
            bulk_cp(st,              A  + ((long)blockIdx.y * Kb + it2) * TILE_FLOATS,
                    TILE_BYTES, mbar);
            bulk_cp(st + TILE_BYTES, Bt + ((long)blockIdx.x * Kb + it2) * TILE_FLOATS,
                    TILE_BYTES, mbar);
        }
    };

    float acc[64];
    #pragma unroll
    for (int i = 0; i < 64; i++) acc[i] = 0.0f;

    fill(0); fill(1);

    for (int it = 0; it < Kb; it++) {
        const int buf = it % STAGES;
        if (it + 2 < Kb) fill(it + 2);    // buf (it-1)%3: reads done (sync below)
        MBARRIER_WAIT_PARITY(sbase + 8 * buf, (it / STAGES) & 1);

        const float* As = sf + (SMEM_BASE / 4) + buf * (STAGE_BYTES / 4);
        const float* Bs = As + TILE_FLOATS;

        #pragma unroll
        for (int kk = 0; kk < 32; kk += 8) {
            const int c0 = (kk + t) ^ sw;
            const int c1 = (kk + t + 4) ^ sw;
            uint32_t ah[16], al[16], bh[8], bl[8];
            #pragma unroll
            for (int mi = 0; mi < 4; mi++) {
                const int r = wm + mi * 16 + g;
                float2 p0 = *reinterpret_cast<const float2*>(As + 2 * (r * 32 + c0));
                float2 p1 = *reinterpret_cast<const float2*>(As + 2 * ((r + 8) * 32 + c0));
                float2 p2 = *reinterpret_cast<const float2*>(As + 2 * (r * 32 + c1));
                float2 p3 = *reinterpret_cast<const float2*>(As + 2 * ((r + 8) * 32 + c1));
                ah[mi*4+0] = __float_as_uint(p0.x); al[mi*4+0] = __float_as_uint(p0.y);
                ah[mi*4+1] = __float_as_uint(p1.x); al[mi*4+1] = __float_as_uint(p1.y);
                ah[mi*4+2] = __float_as_uint(p2.x); al[mi*4+2] = __float_as_uint(p2.y);
                ah[mi*4+3] = __float_as_uint(p3.x); al[mi*4+3] = __float_as_uint(p3.y);
            }
            #pragma unroll
            for (int nj = 0; nj < 4; nj++) {
                const int rr = wn + nj * 8 + g;
                float2 q0 = *reinterpret_cast<const float2*>(Bs + 2 * (rr * 32 + c0));
                float2 q1 = *reinterpret_cast<const float2*>(Bs + 2 * (rr * 32 + c1));
                bh[nj*2+0] = __float_as_uint(q0.x); bl[nj*2+0] = __float_as_uint(q0.y);
                bh[nj*2+1] = __float_as_uint(q1.x); bl[nj*2+1] = __float_as_uint(q1.y);
            }
            #pragma unroll
            for (int mi = 0; mi < 4; mi++)
                #pragma unroll
                for (int nj = 0; nj < 4; nj++) {
                    float* d = acc + (mi * 4 + nj) * 4;
                    mma_tf32(d, &ah[mi * 4], &bh[nj * 2]);   // hi*hi
                    mma_tf32(d, &ah[mi * 4], &bl[nj * 2]);   // hi*lo
                    mma_tf32(d, &al[mi * 4], &bh[nj * 2]);   // lo*hi
                }
        }
        __syncthreads();
    }

    // ---- epilogue ----
    const int m0 = blockIdx.y * 128;
    const int n0 = blockIdx.x * 128;
    #pragma unroll
    for (int mi = 0; mi < 4; mi++) {
        #pragma unroll
        for (int nj = 0; nj < 4; nj++) {
            const float* d = acc + (mi * 4 + nj) * 4;
            const int row = m0 + wm + mi * 16 + g;
            const int col = n0 + wn + nj * 8 + 2 * t;
            if (TILED_C) {
                const int c31 = col & 31;
                #pragma unroll
                for (int h = 0; h < 2; h++) {
                    const int rr = row + 8 * h;
                    const long off = ((long)(rr >> 7) * (N >> 5) + (col >> 5)) * TILE_FLOATS
                                   + 2 * ((rr & 127) * 32 + (c31 ^ ((rr & 7) << 2)));
                    float2 s0 = splitpair(d[2 * h]);
                    float2 s1 = splitpair(d[2 * h + 1]);
                    *reinterpret_cast<float4*>(C + off) = make_float4(s0.x, s0.y, s1.x, s1.y);
                }
            } else {
                *reinterpret_cast<float2*>(C + (long)row * N + col)       = make_float2(d[0], d[1]);
                *reinterpret_cast<float2*>(C + (long)(row + 8) * N + col) = make_float2(d[2], d[3]);
            }
        }
    }
}

// ---------------- retile + split: [rows,C] row-major -> pre-split tiles ----------------
__global__ __launch_bounds__(256) void retile(const float* __restrict__ in,
                                              float* __restrict__ out, int C)
{
    const int rb = blockIdx.y, kb = blockIdx.x;
    float* otile = out + ((long)rb * (C >> 5) + kb) * TILE_FLOATS;
    #pragma unroll
    for (int i = 0; i < 4; i++) {
        const int id = threadIdx.x + 256 * i;   // 0..1023 (float4 units)
        const int r = id >> 3;
        const int c4 = (id & 7) << 2;
        float4 v = *reinterpret_cast<const float4*>(
            in + (long)(rb * 128 + r) * C + kb * 32 + c4);
        float2 s0 = splitpair(v.x), s1 = splitpair(v.y);
        float2 s2 = splitpair(v.z), s3 = splitpair(v.w);
        float* p = otile + 2 * (r * 32 + (c4 ^ ((r & 7) << 2)));
        *reinterpret_cast<float4*>(p)     = make_float4(s0.x, s0.y, s1.x, s1.y);
        *reinterpret_cast<float4*>(p + 4) = make_float4(s2.x, s2.y, s3.x, s3.y);
    }
}

// ---------------- transpose + tile + split: in[R,C] -> pre-split tiles of in^T ----------------
__global__ __launch_bounds__(256) void transpose_tile(
    const float* __restrict__ in, float* __restrict__ out,
    int R, int C, long sIn, long sOut)
{
    __shared__ float tb[32][33];
    const float* ip = in + (long)blockIdx.z * sIn;
    float* op = out + (long)blockIdx.z * sOut;
    const int k0 = blockIdx.x * 32;
    const int n0 = blockIdx.y * 32;
    const int tx = threadIdx.x & 31;
    const int ty = threadIdx.x >> 5;

    #pragma unroll
    for (int i = 0; i < 4; i++)
        tb[ty + 8 * i][tx] = ip[(long)(k0 + ty + 8 * i) * C + n0 + tx];
    __syncthreads();

    const int nb = n0 >> 7, kb = k0 >> 5;
    float* otile = op + ((long)nb * (R >> 5) + kb) * TILE_FLOATS;
    #pragma unroll
    for (int i = 0; i < 4; i++) {
        const int n_loc = ty + 8 * i;
        const int rt = (n0 & 127) + n_loc;
        float2 s = splitpair(tb[tx][n_loc]);
        *reinterpret_cast<float2*>(otile + 2 * (rt * 32 + (tx ^ ((rt & 7) << 2)))) = s;
    }
}

// ---------------- softmax over 2048 cols, in place + pre-split tiled copy ----------------
__inline__ __device__ float warpMax(float v) {
    #pragma unroll
    for (int o = 16; o > 0; o >>= 1) v = fmaxf(v, __shfl_xor_sync(0xffffffffu, v, o));
    return v;
}
__inline__ __device__ float warpSum(float v) {
    #pragma unroll
    for (int o = 16; o > 0; o >>= 1) v += __shfl_xor_sync(0xffffffffu, v, o);
    return v;
}

__global__ __launch_bounds__(256) void softmax2048_dual(
    float* __restrict__ S, float* __restrict__ Wt)
{
    __shared__ float red[8];
    const int b = blockIdx.x >> 11;
    const int q = blockIdx.x & 2047;
    float4* b4 = reinterpret_cast<float4*>(S + (long)blockIdx.x * 2048);

    float4 v0 = b4[threadIdx.x];
    float4 v1 = b4[threadIdx.x + 256];

    float m = fmaxf(fmaxf(fmaxf(v0.x, v0.y), fmaxf(v0.z, v0.w)),
                    fmaxf(fmaxf(v1.x, v1.y), fmaxf(v1.z, v1.w)));
    m = warpMax(m);
    const int wid = threadIdx.x >> 5, lid = threadIdx.x & 31;
    if (lid == 0) red[wid] = m;
    __syncthreads();
    float bm = red[0];
    #pragma unroll
    for (int i = 1; i < 8; i++) bm = fmaxf(bm, red[i]);
    __syncthreads();

    v0.x = __expf(v0.x - bm); v0.y = __expf(v0.y - bm);
    v0.z = __expf(v0.z - bm); v0.w = __expf(v0.w - bm);
    v1.x = __expf(v1.x - bm); v1.y = __expf(v1.y - bm);
    v1.z = __expf(v1.z - bm); v1.w = __expf(v1.w - bm);

    float s = (v0.x + v0.y) + (v0.z + v0.w) + (v1.x + v1.y) + (v1.z + v1.w);
    s = warpSum(s);
    if (lid == 0) red[wid] = s;
    __syncthreads();
    float bs = 0.f;
    #pragma unroll
    for (int i = 0; i < 8; i++) bs += red[i];
    const float inv = 1.0f / bs;

    v0.x *= inv; v0.y *= inv; v0.z *= inv; v0.w *= inv;
    v1.x *= inv; v1.y *= inv; v1.z *= inv; v1.w *= inv;
    b4[threadIdx.x]       = v0;
    b4[threadIdx.x + 256] = v1;

    float* wbase = Wt + (long)2 * b * LQ_ * LK_
                 + ((long)(q >> 7) * (LK_ >> 5)) * TILE_FLOATS
                 + (q & 127) * 64;
    const int swz = (q & 7) << 2;
    #pragma unroll
    for (int h = 0; h < 2; h++) {
        const int c = threadIdx.x * 4 + h * 1024;
        float4 v = h ? v1 : v0;
        float2 s0 = splitpair(v.x), s1 = splitpair(v.y);
        float2 s2 = splitpair(v.z), s3 = splitpair(v.w);
        float* p = wbase + (long)(c >> 5) * TILE_FLOATS + 2 * ((c & 31) ^ swz);
        *reinterpret_cast<float4*>(p)     = make_float4(s0.x, s0.y, s1.x, s1.y);
        *reinterpret_cast<float4*>(p + 4) = make_float4(s2.x, s2.y, s3.x, s3.y);
    }
}

// ---------------- launch ----------------
extern "C" void kernel_launch(void* const* d_in, const int* in_sizes, int n_in,
                              void* d_out, int out_size)
{
    const float* key   = (const float*)d_in[0];
    const float* query = (const float*)d_in[1];
    const float* value = (const float*)d_in[2];
    const float* W     = (const float*)d_in[3];
    // bias (d_in[4]): scalar added to every score -> softmax-invariant -> unused.

    float* weights = (float*)d_out;                   // [B, LQ, LK]
    float* ctx     = weights + (long)B_ * LQ_ * LK_;  // [B, LQ, DV]

    float *qT, *kT, *WtT, *vTT, *qWT, *wT;
    cudaGetSymbolAddress((void**)&qT,  g_qT);
    cudaGetSymbolAddress((void**)&kT,  g_kT);
    cudaGetSymbolAddress((void**)&WtT, g_WtT);
    cudaGetSymbolAddress((void**)&vTT, g_vTT);
    cudaGetSymbolAddress((void**)&qWT, g_qWT);
    cudaGetSymbolAddress((void**)&wT,  g_wT);

    cudaFuncSetAttribute(gemm3x_tf32<true>,  cudaFuncAttributeMaxDynamicSharedMemorySize, GEMM_SMEM);
    cudaFuncSetAttribute(gemm3x_tf32<false>, cudaFuncAttributeMaxDynamicSharedMemorySize, GEMM_SMEM);

    // pre-tiling (+ split)
    retile<<<dim3(D_ / 32, (B_ * LQ_) / 128), 256>>>(query, qT, D_);
    retile<<<dim3(D_ / 32, (B_ * LK_) / 128), 256>>>(key,   kT, D_);
    transpose_tile<<<dim3(D_ / 32, D_ / 32, 1), 256>>>(W, WtT, D_, D_, 0, 0);
    transpose_tile<<<dim3(LK_ / 32, DV_ / 32, B_), 256>>>(
        value, vTT, LK_, DV_, (long)LK_ * DV_, (long)2 * DV_ * LK_);

    // 1) qW = query @ W : output pre-split tiled
    gemm3x_tf32<true><<<dim3(D_ / 128, (B_ * LQ_) / 128, 1), 256, GEMM_SMEM>>>(
        qT, WtT, qWT, B_ * LQ_, D_, D_, 0, 0, 0);

    // 2) scores = qW @ key^T (per batch) -> d_out weights region (row-major)
    gemm3x_tf32<false><<<dim3(LK_ / 128, LQ_ / 128, B_), 256, GEMM_SMEM>>>(
        qWT, kT, weights, LQ_, LK_, D_,
        (long)2 * LQ_ * D_, (long)2 * LK_ * D_, (long)LQ_ * LK_);

    // 3) softmax in place + pre-split tiled copy
    softmax2048_dual<<<B_ * LQ_, 256>>>(weights, wT);

    // 4) ctx = weights @ value (per batch)
    gemm3x_tf32<false><<<dim3(DV_ / 128, LQ_ / 128, B_), 256, GEMM_SMEM>>>(
        wT, vTT, ctx, LQ_, DV_, LK_,
        (long)2 * LQ_ * LK_, (long)2 * DV_ * LK_, (long)LQ_ * DV_);
}

// round 12
// speedup vs baseline: 1.1211x; 1.1211x over previous
#include <cuda_runtime.h>
#include <cstdint>

#define B_   8
#define LQ_  2048
#define LK_  2048
#define D_   1024
#define DV_  1024

// ---------------- tiled scratch (device globals) ----------------
// All tiled arrays: sequence of 16KB tiles [128 rows x 32 floats], element (r,c)
// stored at float offset r*32 + (c ^ ((r&7)<<2)).
__device__ float g_qT [(long)B_ * LQ_ * D_];    // query tiled  [rows/128][K/32]
__device__ float g_kT [(long)B_ * LK_ * D_];    // key tiled (B-side of GEMM2)
__device__ float g_WtT[(long)D_ * D_];          // W^T tiled (B-side of GEMM1)
__device__ float g_vTT[(long)B_ * DV_ * LK_];   // value^T tiled (B-side of GEMM3)
__device__ float g_qWT[(long)B_ * LQ_ * D_];    // qW tiled (A-side of GEMM2)
__device__ float g_wT [(long)B_ * LQ_ * LK_];   // weights tiled (A-side of GEMM3)

// ---------------- helpers ----------------
__device__ __forceinline__ uint32_t smem_u32(const void* p) {
    uint32_t a;
    asm("{ .reg .u64 t; cvta.to.shared.u64 t, %1; cvt.u32.u64 %0, t; }" : "=r"(a) : "l"(p));
    return a;
}

__device__ __forceinline__ uint32_t f2tf32(float x) {
    uint32_t u;
    asm("cvt.rna.tf32.f32 %0, %1;" : "=r"(u) : "f"(x));
    return u;
}

// split fp32 -> (tf32 hi, fp32-bits lo); lo passed raw (HMMA truncates it;
// lo has <=12 significant bits so the truncation residual is ~2^-24 relative).
__device__ __forceinline__ void split_tf32(float x, uint32_t& h, uint32_t& l) {
    h = f2tf32(x);
    l = __float_as_uint(x - __uint_as_float(h));
}

__device__ __forceinline__ void mma_tf32(float* d, const uint32_t* a, const uint32_t* b) {
    asm volatile(
        "mma.sync.aligned.m16n8k8.row.col.f32.tf32.tf32.f32 "
        "{%0,%1,%2,%3}, {%4,%5,%6,%7}, {%8,%9}, {%0,%1,%2,%3};"
        : "+f"(d[0]), "+f"(d[1]), "+f"(d[2]), "+f"(d[3])
        : "r"(a[0]), "r"(a[1]), "r"(a[2]), "r"(a[3]),
          "r"(b[0]), "r"(b[1]));
}

__device__ __forceinline__ void bulk_cp(uint32_t dst, const void* src,
                                        uint32_t bytes, uint32_t mbar) {
    asm volatile("cp.async.bulk.shared::cluster.global.mbarrier::complete_tx::bytes "
                 "[%0], [%1], %2, [%3];"
                 :: "r"(dst), "l"(src), "r"(bytes), "r"(mbar) : "memory");
}

#define MBARRIER_INIT(m, c) \
    asm volatile("mbarrier.init.shared.b64 [%0], %1;" :: "r"(m), "r"(c) : "memory")
#define MBARRIER_EXPECT_TX(m, b) \
    asm volatile("mbarrier.arrive.expect_tx.shared.b64 _, [%0], %1;" :: "r"(m), "r"(b) : "memory")

#define MBARRIER_WAIT_PARITY(mbar_smem_addr, phase_parity) do { \
    uint32_t _mbar = (uint32_t)(mbar_smem_addr); \
    uint32_t _parity = (uint32_t)(phase_parity); \
    uint32_t _done; \
    asm volatile( \
        "{\n\t.reg .pred p;\n\t" \
        "mbarrier.try_wait.parity.acquire.cta.shared::cta.b64 p, [%1], %2;\n\t" \
        "selp.b32 %0, 1, 0, p;\n\t}" \
        : "=r"(_done) : "r"(_mbar), "r"(_parity) : "memory"); \
    if (!_done) { \
        asm volatile( \
            "{\n\t.reg .pred P1;\n\t" \
            "WAIT_LOOP_%=:\n\t" \
            "mbarrier.try_wait.parity.acquire.cta.shared::cta.b64 P1, [%0], %1, 0x989680;\n\t" \
            "@P1 bra.uni WAIT_DONE_%=;\n\t" \
            "bra.uni WAIT_LOOP_%=;\n\t" \
            "WAIT_DONE_%=:\n\t}" \
            :: "r"(_mbar), "r"(_parity) : "memory"); \
    } \
} while (0)

// ---------------- GEMM config ----------------
#define STAGES 4
#define TILE_FLOATS 4096                 // 128 x 32
#define TILE_BYTES  16384
#define STAGE_BYTES (2 * TILE_BYTES)     // A tile + B tile
#define SMEM_BASE   1024                 // mbarriers region
#define GEMM_SMEM   (SMEM_BASE + STAGES * STAGE_BYTES)

// C[M,N] = A[M,K] @ Bt[N,K]^T. A, Bt are TILED (16KB tiles as above).
// 512 threads: 16 warps in a 4x4 grid, each owning a 32x32 sub-tile of the
// 128x128 block tile -> 4 warps per SMSP for latency hiding.
// TILED_C: write C in tiled-swizzled layout too (for feeding the next GEMM).
template<bool TILED_C>
__global__ __launch_bounds__(512, 1) void gemm3x_tf32(
    const float* __restrict__ A, const float* __restrict__ Bt, float* __restrict__ C,
    int M, int N, int K, long sA, long sB, long sC)
{
    extern __shared__ float sf[];
    const uint32_t sbase = smem_u32(sf);

    A  += (long)blockIdx.z * sA;
    Bt += (long)blockIdx.z * sB;
    C  += (long)blockIdx.z * sC;

    const int tid  = threadIdx.x;
    const int lane = tid & 31;
    const int warp = tid >> 5;
    const int g    = lane >> 2;          // 0..7
    const int t    = lane & 3;           // 0..3
    const int sw   = g << 2;             // per-thread column swizzle
    const int wm   = (warp >> 2) * 32;   // warp M offset (0/32/64/96)
    const int wn   = (warp & 3) * 32;    // warp N offset (0/32/64/96)
    const int Kb   = K >> 5;

    if (tid == 0) {
        #pragma unroll
        for (int s = 0; s < STAGES; s++) MBARRIER_INIT(sbase + 8 * s, 1);
    }
    __syncthreads();

    auto fill = [&](int it2) {
        if (tid == 0) {
            const int buf = it2 & (STAGES - 1);
            const uint32_t mbar = sbase + 8 * buf;
            const uint32_t st   = sbase + SMEM_BASE + buf * STAGE_BYTES;
            MBARRIER_EXPECT_TX(mbar, STAGE_BYTES);
            bulk_cp(st,              A  + ((long)blockIdx.y * Kb + it2) * TILE_FLOATS,
                    TILE_BYTES, mbar);
            bulk_cp(st + TILE_BYTES, Bt + ((long)blockIdx.x * Kb + it2) * TILE_FLOATS,
                    TILE_BYTES, mbar);
        }
    };

    float acc[32];
    #pragma unroll
    for (int i = 0; i < 32; i++) acc[i] = 0.0f;

    fill(0); fill(1); fill(2);

    for (int it = 0; it < Kb; it++) {
        const int buf = it & (STAGES - 1);
        if (it + 3 < Kb) fill(it + 3);   // reuses buffer (it-1): reads done (sync below)
        MBARRIER_WAIT_PARITY(sbase + 8 * buf, (it >> 2) & 1);

        const float* As = sf + (SMEM_BASE / 4) + buf * (STAGE_BYTES / 4);
        const float* Bs = As + TILE_FLOATS;

        #pragma unroll
        for (int kk = 0; kk < 32; kk += 8) {
            const int c0 = (kk + t) ^ sw;
            const int c1 = (kk + t + 4) ^ sw;
            uint32_t ah[8], al[8], bh[8], bl[8];
            #pragma unroll
            for (int mi = 0; mi < 2; mi++) {
                const int r = wm + mi * 16 + g;
                split_tf32(As[r * 32 + c0],       ah[mi * 4 + 0], al[mi * 4 + 0]);
                split_tf32(As[(r + 8) * 32 + c0], ah[mi * 4 + 1], al[mi * 4 + 1]);
                split_tf32(As[r * 32 + c1],       ah[mi * 4 + 2], al[mi * 4 + 2]);
                split_tf32(As[(r + 8) * 32 + c1], ah[mi * 4 + 3], al[mi * 4 + 3]);
            }
            #pragma unroll
            for (int nj = 0; nj < 4; nj++) {
                const int rr = wn + nj * 8 + g;
                split_tf32(Bs[rr * 32 + c0], bh[nj * 2 + 0], bl[nj * 2 + 0]);
                split_tf32(Bs[rr * 32 + c1], bh[nj * 2 + 1], bl[nj * 2 + 1]);
            }
            #pragma unroll
            for (int mi = 0; mi < 2; mi++)
                #pragma unroll
                for (int nj = 0; nj < 4; nj++) {
                    float* d = acc + (mi * 4 + nj) * 4;
                    mma_tf32(d, &ah[mi * 4], &bh[nj * 2]);   // hi*hi
                    mma_tf32(d, &ah[mi * 4], &bl[nj * 2]);   // hi*lo
                    mma_tf32(d, &al[mi * 4], &bh[nj * 2]);   // lo*hi
                }
        }
        __syncthreads();
    }

    // ---- epilogue ----
    const int m0 = blockIdx.y * 128;
    const int n0 = blockIdx.x * 128;
    #pragma unroll
    for (int mi = 0; mi < 2; mi++) {
        #pragma unroll
        for (int nj = 0; nj < 4; nj++) {
            const float* d = acc + (mi * 4 + nj) * 4;
            const int row = m0 + wm + mi * 16 + g;
            const int col = n0 + wn + nj * 8 + 2 * t;
            if (TILED_C) {
                // tiled-swizzled write: tile (row>>7, col>>5)
                const int c31 = (col & 31);
                #pragma unroll
                for (int h = 0; h < 2; h++) {
                    const int rr = row + 8 * h;
                    const long off = ((long)(rr >> 7) * (N >> 5) + (col >> 5)) * TILE_FLOATS
                                   + (rr & 127) * 32 + (c31 ^ ((rr & 7) << 2));
                    *reinterpret_cast<float2*>(C + off) = make_float2(d[2 * h], d[2 * h + 1]);
                }
            } else {
                *reinterpret_cast<float2*>(C + (long)row * N + col)       = make_float2(d[0], d[1]);
                *reinterpret_cast<float2*>(C + (long)(row + 8) * N + col) = make_float2(d[2], d[3]);
            }
        }
    }
}

// ---------------- retile: [rows,C] row-major -> tiles [rows/128][C/32] swizzled ----------------
__global__ __launch_bounds__(256) void retile(const float* __restrict__ in,
                                              float* __restrict__ out, int C)
{
    const int rb = blockIdx.y, kb = blockIdx.x;
    float* otile = out + ((long)rb * (C >> 5) + kb) * TILE_FLOATS;
    #pragma unroll
    for (int i = 0; i < 4; i++) {
        const int id = threadIdx.x + 256 * i;   // 0..1023 (float4 units)
        const int r = id >> 3;
        const int c4 = (id & 7) << 2;
        float4 v = *reinterpret_cast<const float4*>(
            in + (long)(rb * 128 + r) * C + kb * 32 + c4);
        *reinterpret_cast<float4*>(otile + r * 32 + (c4 ^ ((r & 7) << 2))) = v;
    }
}

// ---------------- transpose + tile: in[R,C] -> tiles of in^T ([C/128][R/32]) ----------------
__global__ __launch_bounds__(256) void transpose_tile(
    const float* __restrict__ in, float* __restrict__ out,
    int R, int C, long sIn, long sOut)
{
    __shared__ float tb[32][33];
    const float* ip = in + (long)blockIdx.z * sIn;
    float* op = out + (long)blockIdx.z * sOut;
    const int k0 = blockIdx.x * 32;   // row block of in (K dim)
    const int n0 = blockIdx.y * 32;   // col block of in (N dim)
    const int tx = threadIdx.x & 31;
    const int ty = threadIdx.x >> 5;  // 0..7

    #pragma unroll
    for (int i = 0; i < 4; i++)
        tb[ty + 8 * i][tx] = ip[(long)(k0 + ty + 8 * i) * C + n0 + tx];
    __syncthreads();

    const int nb = n0 >> 7, kb = k0 >> 5;
    float* otile = op + ((long)nb * (R >> 5) + kb) * TILE_FLOATS;
    #pragma unroll
    for (int i = 0; i < 4; i++) {
        const int n_loc = ty + 8 * i;
        const int rt = (n0 & 127) + n_loc;
        otile[rt * 32 + (tx ^ ((rt & 7) << 2))] = tb[tx][n_loc];
    }
}

// ---------------- softmax over 2048 cols, in place + tiled-swizzled copy ----------------
__inline__ __device__ float warpMax(float v) {
    #pragma unroll
    for (int o = 16; o > 0; o >>= 1) v = fmaxf(v, __shfl_xor_sync(0xffffffffu, v, o));
    return v;
}
__inline__ __device__ float warpSum(float v) {
    #pragma unroll
    for (int o = 16; o > 0; o >>= 1) v += __shfl_xor_sync(0xffffffffu, v, o);
    return v;
}

__global__ __launch_bounds__(256) void softmax2048_dual(
    float* __restrict__ S, float* __restrict__ Wt)
{
    __shared__ float red[8];
    const int b = blockIdx.x >> 11;
    const int q = blockIdx.x & 2047;
    float4* b4 = reinterpret_cast<float4*>(S + (long)blockIdx.x * 2048);

    float4 v0 = b4[threadIdx.x];
    float4 v1 = b4[threadIdx.x + 256];

    float m = fmaxf(fmaxf(fmaxf(v0.x, v0.y), fmaxf(v0.z, v0.w)),
                    fmaxf(fmaxf(v1.x, v1.y), fmaxf(v1.z, v1.w)));
    m = warpMax(m);
    const int wid = threadIdx.x >> 5, lid = threadIdx.x & 31;
    if (lid == 0) red[wid] = m;
    __syncthreads();
    float bm = red[0];
    #pragma unroll
    for (int i = 1; i < 8; i++) bm = fmaxf(bm, red[i]);
    __syncthreads();

    v0.x = __expf(v0.x - bm); v0.y = __expf(v0.y - bm);
    v0.z = __expf(v0.z - bm); v0.w = __expf(v0.w - bm);
    v1.x = __expf(v1.x - bm); v1.y = __expf(v1.y - bm);
    v1.z = __expf(v1.z - bm); v1.w = __expf(v1.w - bm);

    float s = (v0.x + v0.y) + (v0.z + v0.w) + (v1.x + v1.y) + (v1.z + v1.w);
    s = warpSum(s);
    if (lid == 0) red[wid] = s;
    __syncthreads();
    float bs = 0.f;
    #pragma unroll
    for (int i = 0; i < 8; i++) bs += red[i];
    const float inv = 1.0f / bs;

    v0.x *= inv; v0.y *= inv; v0.z *= inv; v0.w *= inv;
    v1.x *= inv; v1.y *= inv; v1.z *= inv; v1.w *= inv;
    b4[threadIdx.x]       = v0;
    b4[threadIdx.x + 256] = v1;

    // tiled copy: row q, cols 4*tid and 4*tid+1024
    float* wbase = Wt + (long)b * LQ_ * LK_
                 + ((long)(q >> 7) * (LK_ >> 5)) * TILE_FLOATS
                 + (q & 127) * 32;
    const int swz = (q & 7) << 2;
    {
        const int c = threadIdx.x * 4;
        float* p = wbase + (long)(c >> 5) * TILE_FLOATS + ((c & 31) ^ swz);
        *reinterpret_cast<float4*>(p) = v0;
    }
    {
        const int c = threadIdx.x * 4 + 1024;
        float* p = wbase + (long)(c >> 5) * TILE_FLOATS + ((c & 31) ^ swz);
        *reinterpret_cast<float4*>(p) = v1;
    }
}

// ---------------- launch ----------------
extern "C" void kernel_launch(void* const* d_in, const int* in_sizes, int n_in,
                              void* d_out, int out_size)
{
    const float* key   = (const float*)d_in[0];
    const float* query = (const float*)d_in[1];
    const float* value = (const float*)d_in[2];
    const float* W     = (const float*)d_in[3];
    // bias (d_in[4]): scalar added to every score -> softmax-invariant -> unused.

    float* weights = (float*)d_out;                   // [B, LQ, LK]
    float* ctx     = weights + (long)B_ * LQ_ * LK_;  // [B, LQ, DV]

    float *qT, *kT, *WtT, *vTT, *qWT, *wT;
    cudaGetSymbolAddress((void**)&qT,  g_qT);
    cudaGetSymbolAddress((void**)&kT,  g_kT);
    cudaGetSymbolAddress((void**)&WtT, g_WtT);
    cudaGetSymbolAddress((void**)&vTT, g_vTT);
    cudaGetSymbolAddress((void**)&qWT, g_qWT);
    cudaGetSymbolAddress((void**)&wT,  g_wT);

    cudaFuncSetAttribute(gemm3x_tf32<true>,  cudaFuncAttributeMaxDynamicSharedMemorySize, GEMM_SMEM);
    cudaFuncSetAttribute(gemm3x_tf32<false>, cudaFuncAttributeMaxDynamicSharedMemorySize, GEMM_SMEM);

    // pre-tiling
    retile<<<dim3(D_ / 32, (B_ * LQ_) / 128), 256>>>(query, qT, D_);
    retile<<<dim3(D_ / 32, (B_ * LK_) / 128), 256>>>(key,   kT, D_);
    transpose_tile<<<dim3(D_ / 32, D_ / 32, 1), 256>>>(W, WtT, D_, D_, 0, 0);
    transpose_tile<<<dim3(LK_ / 32, DV_ / 32, B_), 256>>>(
        value, vTT, LK_, DV_, (long)LK_ * DV_, (long)DV_ * LK_);

    // 1) qW = query @ W : [16384,1024] x [1024,1024], output tiled
    gemm3x_tf32<true><<<dim3(D_ / 128, (B_ * LQ_) / 128, 1), 512, GEMM_SMEM>>>(
        qT, WtT, qWT, B_ * LQ_, D_, D_, 0, 0, 0);

    // 2) scores = qW @ key^T (per batch) -> d_out weights region (row-major)
    gemm3x_tf32<false><<<dim3(LK_ / 128, LQ_ / 128, B_), 512, GEMM_SMEM>>>(
        qWT, kT, weights, LQ_, LK_, D_,
        (long)LQ_ * D_, (long)LK_ * D_, (long)LQ_ * LK_);

    // 3) softmax in place + tiled copy
    softmax2048_dual<<<B_ * LQ_, 256>>>(weights, wT);

    // 4) ctx = weights @ value (per batch)
    gemm3x_tf32<false><<<dim3(DV_ / 128, LQ_ / 128, B_), 512, GEMM_SMEM>>>(
        wT, vTT, ctx, LQ_, DV_, LK_,
        (long)LQ_ * LK_, (long)LK_ * DV_, (long)LQ_ * DV_);
}

// round 13
// speedup vs baseline: 1.2142x; 1.0830x over previous
#include <cuda_runtime.h>
#include <cstdint>

#define B_   8
#define LQ_  2048
#define LK_  2048
#define D_   1024
#define DV_  1024

// ---------------- tiled scratch (device globals) ----------------
// All tiled arrays: sequence of 16KB tiles [128 rows x 32 floats], element (r,c)
// stored at float offset r*32 + (c ^ ((r&7)<<2)).
__device__ float g_qT [(long)B_ * LQ_ * D_];    // query tiled  [rows/128][K/32]
__device__ float g_kT [(long)B_ * LK_ * D_];    // key tiled (B-side of GEMM2)
__device__ float g_WtT[(long)D_ * D_];          // W^T tiled (B-side of GEMM1)
__device__ float g_vTT[(long)B_ * DV_ * LK_];   // value^T tiled (B-side of GEMM3)
__device__ float g_qWT[(long)B_ * LQ_ * D_];    // qW tiled (A-side of GEMM2)
__device__ float g_wT [(long)B_ * LQ_ * LK_];   // weights tiled (A-side of GEMM3)

// ---------------- helpers ----------------
__device__ __forceinline__ uint32_t smem_u32(const void* p) {
    uint32_t a;
    asm("{ .reg .u64 t; cvta.to.shared.u64 t, %1; cvt.u32.u64 %0, t; }" : "=r"(a) : "l"(p));
    return a;
}

__device__ __forceinline__ uint32_t f2tf32(float x) {
    uint32_t u;
    asm("cvt.rna.tf32.f32 %0, %1;" : "=r"(u) : "f"(x));
    return u;
}

// split fp32 -> (tf32 hi, fp32-bits lo); lo passed raw (HMMA truncates it;
// lo has <=12 significant bits so the truncation residual is ~2^-24 relative).
__device__ __forceinline__ void split_tf32(float x, uint32_t& h, uint32_t& l) {
    h = f2tf32(x);
    l = __float_as_uint(x - __uint_as_float(h));
}

__device__ __forceinline__ void mma_tf32(float* d, const uint32_t* a, const uint32_t* b) {
    asm volatile(
        "mma.sync.aligned.m16n8k8.row.col.f32.tf32.tf32.f32 "
        "{%0,%1,%2,%3}, {%4,%5,%6,%7}, {%8,%9}, {%0,%1,%2,%3};"
        : "+f"(d[0]), "+f"(d[1]), "+f"(d[2]), "+f"(d[3])
        : "r"(a[0]), "r"(a[1]), "r"(a[2]), "r"(a[3]),
          "r"(b[0]), "r"(b[1]));
}

__device__ __forceinline__ void bulk_cp(uint32_t dst, const void* src,
                                        uint32_t bytes, uint32_t mbar) {
    asm volatile("cp.async.bulk.shared::cluster.global.mbarrier::complete_tx::bytes "
                 "[%0], [%1], %2, [%3];"
                 :: "r"(dst), "l"(src), "r"(bytes), "r"(mbar) : "memory");
}

#define MBARRIER_INIT(m, c) \
    asm volatile("mbarrier.init.shared.b64 [%0], %1;" :: "r"(m), "r"(c) : "memory")
#define MBARRIER_EXPECT_TX(m, b) \
    asm volatile("mbarrier.arrive.expect_tx.shared.b64 _, [%0], %1;" :: "r"(m), "r"(b) : "memory")

#define MBARRIER_WAIT_PARITY(mbar_smem_addr, phase_parity) do { \
    uint32_t _mbar = (uint32_t)(mbar_smem_addr); \
    uint32_t _parity = (uint32_t)(phase_parity); \
    uint32_t _done; \
    asm volatile( \
        "{\n\t.reg .pred p;\n\t" \
        "mbarrier.try_wait.parity.acquire.cta.shared::cta.b64 p, [%1], %2;\n\t" \
        "selp.b32 %0, 1, 0, p;\n\t}" \
        : "=r"(_done) : "r"(_mbar), "r"(_parity) : "memory"); \
    if (!_done) { \
        asm volatile( \
            "{\n\t.reg .pred P1;\n\t" \
            "WAIT_LOOP_%=:\n\t" \
            "mbarrier.try_wait.parity.acquire.cta.shared::cta.b64 P1, [%0], %1, 0x989680;\n\t" \
            "@P1 bra.uni WAIT_DONE_%=;\n\t" \
            "bra.uni WAIT_LOOP_%=;\n\t" \
            "WAIT_DONE_%=:\n\t}" \
            :: "r"(_mbar), "r"(_parity) : "memory"); \
    } \
} while (0)

// ---------------- GEMM config ----------------
#define STAGES 3
#define TILE_FLOATS 4096                 // 128 x 32
#define TILE_BYTES  16384
#define STAGE_BYTES (2 * TILE_BYTES)     // A tile + B tile
#define SMEM_BASE   1024                 // mbarriers region
#define GEMM_SMEM   (SMEM_BASE + STAGES * STAGE_BYTES)   // 99328 -> 2 CTAs/SM

// C[M,N] = A[M,K] @ Bt[N,K]^T. A, Bt are TILED (16KB tiles as above).
// 256 threads, 8 warps in 2x4 grid, each owning a 64x32 sub-tile.
// 3-stage pipeline @ 99KB smem -> 2 CTAs resident per SM (4 warps/SMSP).
// TILED_C: write C in tiled-swizzled layout too (for feeding the next GEMM).
template<bool TILED_C>
__global__ __launch_bounds__(256, 2) void gemm3x_tf32(
    const float* __restrict__ A, const float* __restrict__ Bt, float* __restrict__ C,
    int M, int N, int K, long sA, long sB, long sC)
{
    extern __shared__ float sf[];
    const uint32_t sbase = smem_u32(sf);

    A  += (long)blockIdx.z * sA;
    Bt += (long)blockIdx.z * sB;
    C  += (long)blockIdx.z * sC;

    const int tid  = threadIdx.x;
    const int lane = tid & 31;
    const int warp = tid >> 5;
    const int g    = lane >> 2;          // 0..7
    const int t    = lane & 3;           // 0..3
    const int sw   = g << 2;             // per-thread column swizzle
    const int wm   = (warp >> 2) * 64;   // warp M offset (0/64)
    const int wn   = (warp & 3) * 32;    // warp N offset (0/32/64/96)
    const int Kb   = K >> 5;

    if (tid == 0) {
        #pragma unroll
        for (int s = 0; s < STAGES; s++) MBARRIER_INIT(sbase + 8 * s, 1);
    }
    __syncthreads();

    auto fill = [&](int it2) {
        if (tid == 0) {
            const int buf = it2 % STAGES;
            const uint32_t mbar = sbase + 8 * buf;
            const uint32_t st   = sbase + SMEM_BASE + buf * STAGE_BYTES;
            MBARRIER_EXPECT_TX(mbar, STAGE_BYTES);
            bulk_cp(st,              A  + ((long)blockIdx.y * Kb + it2) * TILE_FLOATS,
                    TILE_BYTES, mbar);
            bulk_cp(st + TILE_BYTES, Bt + ((long)blockIdx.x * Kb + it2) * TILE_FLOATS,
                    TILE_BYTES, mbar);
        }
    };

    float acc[64];
    #pragma unroll
    for (int i = 0; i < 64; i++) acc[i] = 0.0f;

    fill(0); fill(1);

    for (int it = 0; it < Kb; it++) {
        const int buf = it % STAGES;
        if (it + 2 < Kb) fill(it + 2);   // buf (it-1)%3: reads done (sync below)
        MBARRIER_WAIT_PARITY(sbase + 8 * buf, (it / STAGES) & 1);

        const float* As = sf + (SMEM_BASE / 4) + buf * (STAGE_BYTES / 4);
        const float* Bs = As + TILE_FLOATS;

        #pragma unroll
        for (int kk = 0; kk < 32; kk += 8) {
            const int c0 = (kk + t) ^ sw;
            const int c1 = (kk + t + 4) ^ sw;
            uint32_t ah[16], al[16], bh[8], bl[8];
            #pragma unroll
            for (int mi = 0; mi < 4; mi++) {
                const int r = wm + mi * 16 + g;
                split_tf32(As[r * 32 + c0],       ah[mi * 4 + 0], al[mi * 4 + 0]);
                split_tf32(As[(r + 8) * 32 + c0], ah[mi * 4 + 1], al[mi * 4 + 1]);
                split_tf32(As[r * 32 + c1],       ah[mi * 4 + 2], al[mi * 4 + 2]);
                split_tf32(As[(r + 8) * 32 + c1], ah[mi * 4 + 3], al[mi * 4 + 3]);
            }
            #pragma unroll
            for (int nj = 0; nj < 4; nj++) {
                const int rr = wn + nj * 8 + g;
                split_tf32(Bs[rr * 32 + c0], bh[nj * 2 + 0], bl[nj * 2 + 0]);
                split_tf32(Bs[rr * 32 + c1], bh[nj * 2 + 1], bl[nj * 2 + 1]);
            }
            #pragma unroll
            for (int mi = 0; mi < 4; mi++)
                #pragma unroll
                for (int nj = 0; nj < 4; nj++) {
                    float* d = acc + (mi * 4 + nj) * 4;
                    mma_tf32(d, &ah[mi * 4], &bh[nj * 2]);   // hi*hi
                    mma_tf32(d, &ah[mi * 4], &bl[nj * 2]);   // hi*lo
                    mma_tf32(d, &al[mi * 4], &bh[nj * 2]);   // lo*hi
                }
        }
        __syncthreads();
    }

    // ---- epilogue ----
    const int m0 = blockIdx.y * 128;
    const int n0 = blockIdx.x * 128;
    #pragma unroll
    for (int mi = 0; mi < 4; mi++) {
        #pragma unroll
        for (int nj = 0; nj < 4; nj++) {
            const float* d = acc + (mi * 4 + nj) * 4;
            const int row = m0 + wm + mi * 16 + g;
            const int col = n0 + wn + nj * 8 + 2 * t;
            if (TILED_C) {
                // tiled-swizzled write: tile (row>>7, col>>5)
                const int c31 = (col & 31);
                #pragma unroll
                for (int h = 0; h < 2; h++) {
                    const int rr = row + 8 * h;
                    const long off = ((long)(rr >> 7) * (N >> 5) + (col >> 5)) * TILE_FLOATS
                                   + (rr & 127) * 32 + (c31 ^ ((rr & 7) << 2));
                    *reinterpret_cast<float2*>(C + off) = make_float2(d[2 * h], d[2 * h + 1]);
                }
            } else {
                *reinterpret_cast<float2*>(C + (long)row * N + col)       = make_float2(d[0], d[1]);
                *reinterpret_cast<float2*>(C + (long)(row + 8) * N + col) = make_float2(d[2], d[3]);
            }
        }
    }
}

// ---------------- retile: [rows,C] row-major -> tiles [rows/128][C/32] swizzled ----------------
__global__ __launch_bounds__(256) void retile(const float* __restrict__ in,
                                              float* __restrict__ out, int C)
{
    const int rb = blockIdx.y, kb = blockIdx.x;
    float* otile = out + ((long)rb * (C >> 5) + kb) * TILE_FLOATS;
    #pragma unroll
    for (int i = 0; i < 4; i++) {
        const int id = threadIdx.x + 256 * i;   // 0..1023 (float4 units)
        const int r = id >> 3;
        const int c4 = (id & 7) << 2;
        float4 v = *reinterpret_cast<const float4*>(
            in + (long)(rb * 128 + r) * C + kb * 32 + c4);
        *reinterpret_cast<float4*>(otile + r * 32 + (c4 ^ ((r & 7) << 2))) = v;
    }
}

// ---------------- transpose + tile: in[R,C] -> tiles of in^T ([C/128][R/32]) ----------------
__global__ __launch_bounds__(256) void transpose_tile(
    const float* __restrict__ in, float* __restrict__ out,
    int R, int C, long sIn, long sOut)
{
    __shared__ float tb[32][33];
    const float* ip = in + (long)blockIdx.z * sIn;
    float* op = out + (long)blockIdx.z * sOut;
    const int k0 = blockIdx.x * 32;   // row block of in (K dim)
    const int n0 = blockIdx.y * 32;   // col block of in (N dim)
    const int tx = threadIdx.x & 31;
    const int ty = threadIdx.x >> 5;  // 0..7

    #pragma unroll
    for (int i = 0; i < 4; i++)
        tb[ty + 8 * i][tx] = ip[(long)(k0 + ty + 8 * i) * C + n0 + tx];
    __syncthreads();

    const int nb = n0 >> 7, kb = k0 >> 5;
    float* otile = op + ((long)nb * (R >> 5) + kb) * TILE_FLOATS;
    #pragma unroll
    for (int i = 0; i < 4; i++) {
        const int n_loc = ty + 8 * i;
        const int rt = (n0 & 127) + n_loc;
        otile[rt * 32 + (tx ^ ((rt & 7) << 2))] = tb[tx][n_loc];
    }
}

// ---------------- softmax over 2048 cols, in place + tiled-swizzled copy ----------------
__inline__ __device__ float warpMax(float v) {
    #pragma unroll
    for (int o = 16; o > 0; o >>= 1) v = fmaxf(v, __shfl_xor_sync(0xffffffffu, v, o));
    return v;
}
__inline__ __device__ float warpSum(float v) {
    #pragma unroll
    for (int o = 16; o > 0; o >>= 1) v += __shfl_xor_sync(0xffffffffu, v, o);
    return v;
}

__global__ __launch_bounds__(256) void softmax2048_dual(
    float* __restrict__ S, float* __restrict__ Wt)
{
    __shared__ float red[8];
    const int b = blockIdx.x >> 11;
    const int q = blockIdx.x & 2047;
    float4* b4 = reinterpret_cast<float4*>(S + (long)blockIdx.x * 2048);

    float4 v0 = b4[threadIdx.x];
    float4 v1 = b4[threadIdx.x + 256];

    float m = fmaxf(fmaxf(fmaxf(v0.x, v0.y), fmaxf(v0.z, v0.w)),
                    fmaxf(fmaxf(v1.x, v1.y), fmaxf(v1.z, v1.w)));
    m = warpMax(m);
    const int wid = threadIdx.x >> 5, lid = threadIdx.x & 31;
    if (lid == 0) red[wid] = m;
    __syncthreads();
    float bm = red[0];
    #pragma unroll
    for (int i = 1; i < 8; i++) bm = fmaxf(bm, red[i]);
    __syncthreads();

    v0.x = __expf(v0.x - bm); v0.y = __expf(v0.y - bm);
    v0.z = __expf(v0.z - bm); v0.w = __expf(v0.w - bm);
    v1.x = __expf(v1.x - bm); v1.y = __expf(v1.y - bm);
    v1.z = __expf(v1.z - bm); v1.w = __expf(v1.w - bm);

    float s = (v0.x + v0.y) + (v0.z + v0.w) + (v1.x + v1.y) + (v1.z + v1.w);
    s = warpSum(s);
    if (lid == 0) red[wid] = s;
    __syncthreads();
    float bs = 0.f;
    #pragma unroll
    for (int i = 0; i < 8; i++) bs += red[i];
    const float inv = 1.0f / bs;

    v0.x *= inv; v0.y *= inv; v0.z *= inv; v0.w *= inv;
    v1.x *= inv; v1.y *= inv; v1.z *= inv; v1.w *= inv;
    b4[threadIdx.x]       = v0;
    b4[threadIdx.x + 256] = v1;

    // tiled copy: row q, cols 4*tid and 4*tid+1024
    float* wbase = Wt + (long)b * LQ_ * LK_
                 + ((long)(q >> 7) * (LK_ >> 5)) * TILE_FLOATS
                 + (q & 127) * 32;
    const int swz = (q & 7) << 2;
    {
        const int c = threadIdx.x * 4;
        float* p = wbase + (long)(c >> 5) * TILE_FLOATS + ((c & 31) ^ swz);
        *reinterpret_cast<float4*>(p) = v0;
    }
    {
        const int c = threadIdx.x * 4 + 1024;
        float* p = wbase + (long)(c >> 5) * TILE_FLOATS + ((c & 31) ^ swz);
        *reinterpret_cast<float4*>(p) = v1;
    }
}

// ---------------- launch ----------------
extern "C" void kernel_launch(void* const* d_in, const int* in_sizes, int n_in,
                              void* d_out, int out_size)
{
    const float* key   = (const float*)d_in[0];
    const float* query = (const float*)d_in[1];
    const float* value = (const float*)d_in[2];
    const float* W     = (const float*)d_in[3];
    // bias (d_in[4]): scalar added to every score -> softmax-invariant -> unused.

    float* weights = (float*)d_out;                   // [B, LQ, LK]
    float* ctx     = weights + (long)B_ * LQ_ * LK_;  // [B, LQ, DV]

    float *qT, *kT, *WtT, *vTT, *qWT, *wT;
    cudaGetSymbolAddress((void**)&qT,  g_qT);
    cudaGetSymbolAddress((void**)&kT,  g_kT);
    cudaGetSymbolAddress((void**)&WtT, g_WtT);
    cudaGetSymbolAddress((void**)&vTT, g_vTT);
    cudaGetSymbolAddress((void**)&qWT, g_qWT);
    cudaGetSymbolAddress((void**)&wT,  g_wT);

    cudaFuncSetAttribute(gemm3x_tf32<true>,  cudaFuncAttributeMaxDynamicSharedMemorySize, GEMM_SMEM);
    cudaFuncSetAttribute(gemm3x_tf32<false>, cudaFuncAttributeMaxDynamicSharedMemorySize, GEMM_SMEM);

    // pre-tiling
    retile<<<dim3(D_ / 32, (B_ * LQ_) / 128), 256>>>(query, qT, D_);
    retile<<<dim3(D_ / 32, (B_ * LK_) / 128), 256>>>(key,   kT, D_);
    transpose_tile<<<dim3(D_ / 32, D_ / 32, 1), 256>>>(W, WtT, D_, D_, 0, 0);
    transpose_tile<<<dim3(LK_ / 32, DV_ / 32, B_), 256>>>(
        value, vTT, LK_, DV_, (long)LK_ * DV_, (long)DV_ * LK_);

    // 1) qW = query @ W : [16384,1024] x [1024,1024], output tiled
    gemm3x_tf32<true><<<dim3(D_ / 128, (B_ * LQ_) / 128, 1), 256, GEMM_SMEM>>>(
        qT, WtT, qWT, B_ * LQ_, D_, D_, 0, 0, 0);

    // 2) scores = qW @ key^T (per batch) -> d_out weights region (row-major)
    gemm3x_tf32<false><<<dim3(LK_ / 128, LQ_ / 128, B_), 256, GEMM_SMEM>>>(
        qWT, kT, weights, LQ_, LK_, D_,
        (long)LQ_ * D_, (long)LK_ * D_, (long)LQ_ * LK_);

    // 3) softmax in place + tiled copy
    softmax2048_dual<<<B_ * LQ_, 256>>>(weights, wT);

    // 4) ctx = weights @ value (per batch)
    gemm3x_tf32<false><<<dim3(DV_ / 128, LQ_ / 128, B_), 256, GEMM_SMEM>>>(
        wT, vTT, ctx, LQ_, DV_, LK_,
        (long)LQ_ * LK_, (long)LK_ * DV_, (long)LQ_ * DV_);
}

// round 14
// speedup vs baseline: 2.4854x; 2.0469x over previous
#include <cuda_runtime.h>
#include <cuda_fp16.h>
#include <cstdint>

#define B_   8
#define LQ_  2048
#define LK_  2048
#define D_   1024
#define DV_  1024

// ---------------- tiled scratch (device globals) ----------------
// Tile = 16KB = [hi plane: 128 rows x 16 half2 words][lo plane: same].
// Element (r,c): half goes in word w=c>>1 (low half = even c), stored at
// word offset r*16 + (w ^ ((r&7)<<1)); lo plane at +2048 words.
__device__ uint32_t g_qT [(long)B_ * LQ_ * D_];    // query tiled (A of G1)
__device__ uint32_t g_kT [(long)B_ * LK_ * D_];    // key tiled (B of G2)
__device__ uint32_t g_WtT[(long)D_ * D_];          // W^T tiled (B of G1)
__device__ uint32_t g_vTT[(long)B_ * DV_ * LK_];   // value^T tiled (B of G3)
__device__ uint32_t g_qWT[(long)B_ * LQ_ * D_];    // qW tiled (A of G2)
__device__ uint32_t g_wT [(long)B_ * LQ_ * LK_];   // weights tiled (A of G3)

// ---------------- helpers ----------------
__device__ __forceinline__ uint32_t smem_u32(const void* p) {
    uint32_t a;
    asm("{ .reg .u64 t; cvta.to.shared.u64 t, %1; cvt.u32.u64 %0, t; }" : "=r"(a) : "l"(p));
    return a;
}

// split two fp32 -> packed f16 hi word + f16 lo word (lo = x - f32(hi), next 11 bits)
__device__ __forceinline__ void split2(float x0, float x1, uint32_t& hw, uint32_t& lw) {
    __half2 h = __floats2half2_rn(x0, x1);           // .x (low) = x0
    float2 hf = __half22float2(h);
    __half2 l = __floats2half2_rn(x0 - hf.x, x1 - hf.y);
    hw = *reinterpret_cast<uint32_t*>(&h);
    lw = *reinterpret_cast<uint32_t*>(&l);
}

__device__ __forceinline__ void mma_f16(float* d, const uint32_t* a, const uint32_t* b) {
    asm volatile(
        "mma.sync.aligned.m16n8k16.row.col.f32.f16.f16.f32 "
        "{%0,%1,%2,%3}, {%4,%5,%6,%7}, {%8,%9}, {%0,%1,%2,%3};"
        : "+f"(d[0]), "+f"(d[1]), "+f"(d[2]), "+f"(d[3])
        : "r"(a[0]), "r"(a[1]), "r"(a[2]), "r"(a[3]),
          "r"(b[0]), "r"(b[1]));
}

__device__ __forceinline__ void bulk_cp(uint32_t dst, const void* src,
                                        uint32_t bytes, uint32_t mbar) {
    asm volatile("cp.async.bulk.shared::cluster.global.mbarrier::complete_tx::bytes "
                 "[%0], [%1], %2, [%3];"
                 :: "r"(dst), "l"(src), "r"(bytes), "r"(mbar) : "memory");
}

#define MBARRIER_INIT(m, c) \
    asm volatile("mbarrier.init.shared.b64 [%0], %1;" :: "r"(m), "r"(c) : "memory")
#define MBARRIER_EXPECT_TX(m, b) \
    asm volatile("mbarrier.arrive.expect_tx.shared.b64 _, [%0], %1;" :: "r"(m), "r"(b) : "memory")

#define MBARRIER_WAIT_PARITY(mbar_smem_addr, phase_parity) do { \
    uint32_t _mbar = (uint32_t)(mbar_smem_addr); \
    uint32_t _parity = (uint32_t)(phase_parity); \
    uint32_t _done; \
    asm volatile( \
        "{\n\t.reg .pred p;\n\t" \
        "mbarrier.try_wait.parity.acquire.cta.shared::cta.b64 p, [%1], %2;\n\t" \
        "selp.b32 %0, 1, 0, p;\n\t}" \
        : "=r"(_done) : "r"(_mbar), "r"(_parity) : "memory"); \
    if (!_done) { \
        asm volatile( \
            "{\n\t.reg .pred P1;\n\t" \
            "WAIT_LOOP_%=:\n\t" \
            "mbarrier.try_wait.parity.acquire.cta.shared::cta.b64 P1, [%0], %1, 0x989680;\n\t" \
            "@P1 bra.uni WAIT_DONE_%=;\n\t" \
            "bra.uni WAIT_LOOP_%=;\n\t" \
            "WAIT_DONE_%=:\n\t}" \
            :: "r"(_mbar), "r"(_parity) : "memory"); \
    } \
} while (0)

// ---------------- GEMM config ----------------
#define STAGES 3
#define TILE_WORDS 4096                  // 16KB: hi 2048 + lo 2048
#define TILE_BYTES  16384
#define STAGE_BYTES (2 * TILE_BYTES)     // A tile + B tile
#define SMEM_BASE   1024
#define GEMM_SMEM   (SMEM_BASE + STAGES * STAGE_BYTES)   // 99328 -> 2 CTAs/SM

// C[M,N] = A[M,K] @ Bt[N,K]^T. A, Bt pre-split fp16 hi/lo tiled (above).
// 3xFP16 emulation: D += Ahi*Bhi + Ahi*Blo + Alo*Bhi (fp32 accum).
// 256 thr, 8 warps 2x4, 64x32 warp tiles; 96 HMMA.16816 per warp per iter.
template<bool TILED_C>
__global__ __launch_bounds__(256, 2) void gemm3x_f16(
    const uint32_t* __restrict__ A, const uint32_t* __restrict__ Bt, float* __restrict__ C,
    int M, int N, int K, long sA, long sB, long sC)
{
    extern __shared__ float sf[];
    const uint32_t sbase = smem_u32(sf);

    A  += (long)blockIdx.z * sA;
    Bt += (long)blockIdx.z * sB;
    C  += (long)blockIdx.z * sC;

    const int tid  = threadIdx.x;
    const int lane = tid & 31;
    const int warp = tid >> 5;
    const int g    = lane >> 2;          // 0..7
    const int t    = lane & 3;           // 0..3
    const int sw2  = g << 1;             // word swizzle for rows (r&7)==g
    const int wm   = (warp >> 2) * 64;   // warp M offset (0/64)
    const int wn   = (warp & 3) * 32;    // warp N offset (0/32/64/96)
    const int Kb   = K >> 5;

    if (tid == 0) {
        #pragma unroll
        for (int s = 0; s < STAGES; s++) MBARRIER_INIT(sbase + 8 * s, 1);
    }
    __syncthreads();

    auto fill = [&](int it2) {
        if (tid == 0) {
            const int buf = it2 % STAGES;
            const uint32_t mbar = sbase + 8 * buf;
            const uint32_t st   = sbase + SMEM_BASE + buf * STAGE_BYTES;
            MBARRIER_EXPECT_TX(mbar, STAGE_BYTES);
            bulk_cp(st,              A  + ((long)blockIdx.y * Kb + it2) * TILE_WORDS,
                    TILE_BYTES, mbar);
            bulk_cp(st + TILE_BYTES, Bt + ((long)blockIdx.x * Kb + it2) * TILE_WORDS,
                    TILE_BYTES, mbar);
        }
    };

    float acc[64];
    #pragma unroll
    for (int i = 0; i < 64; i++) acc[i] = 0.0f;

    fill(0); fill(1);

    for (int it = 0; it < Kb; it++) {
        const int buf = it % STAGES;
        if (it + 2 < Kb) fill(it + 2);   // buf (it-1)%3: reads done (sync below)
        MBARRIER_WAIT_PARITY(sbase + 8 * buf, (it / STAGES) & 1);

        const uint32_t* Ts = reinterpret_cast<const uint32_t*>(sf)
                           + (SMEM_BASE / 4) + buf * (STAGE_BYTES / 4);
        const uint32_t* Ahp = Ts;            // A hi plane (2048 words)
        const uint32_t* Alp = Ts + 2048;     // A lo plane
        const uint32_t* Bhp = Ts + 4096;     // B hi plane
        const uint32_t* Blp = Ts + 6144;     // B lo plane

        #pragma unroll
        for (int kk = 0; kk < 2; kk++) {     // two K=16 steps per 32-K tile
            const int wb = kk * 8;
            const int w0 = (wb + t) ^ sw2;
            const int w1 = (wb + t + 4) ^ sw2;
            uint32_t ah[16], al[16], bh[8], bl[8];
            #pragma unroll
            for (int mi = 0; mi < 4; mi++) {
                const int r16  = (wm + mi * 16 + g) * 16;
                const int r16b = r16 + 128;  // (+8 rows) * 16
                ah[mi*4+0] = Ahp[r16 + w0];  ah[mi*4+1] = Ahp[r16b + w0];
                ah[mi*4+2] = Ahp[r16 + w1];  ah[mi*4+3] = Ahp[r16b + w1];
                al[mi*4+0] = Alp[r16 + w0];  al[mi*4+1] = Alp[r16b + w0];
                al[mi*4+2] = Alp[r16 + w1];  al[mi*4+3] = Alp[r16b + w1];
            }
            #pragma unroll
            for (int nj = 0; nj < 4; nj++) {
                const int rr16 = (wn + nj * 8 + g) * 16;
                bh[nj*2+0] = Bhp[rr16 + w0]; bh[nj*2+1] = Bhp[rr16 + w1];
                bl[nj*2+0] = Blp[rr16 + w0]; bl[nj*2+1] = Blp[rr16 + w1];
            }
            #pragma unroll
            for (int mi = 0; mi < 4; mi++)
                #pragma unroll
                for (int nj = 0; nj < 4; nj++) {
                    float* d = acc + (mi * 4 + nj) * 4;
                    mma_f16(d, &ah[mi * 4], &bh[nj * 2]);   // hi*hi
                    mma_f16(d, &ah[mi * 4], &bl[nj * 2]);   // hi*lo
                    mma_f16(d, &al[mi * 4], &bh[nj * 2]);   // lo*hi
                }
        }
        __syncthreads();
    }

    // ---- epilogue ----
    const int m0 = blockIdx.y * 128;
    const int n0 = blockIdx.x * 128;
    #pragma unroll
    for (int mi = 0; mi < 4; mi++) {
        #pragma unroll
        for (int nj = 0; nj < 4; nj++) {
            const float* d = acc + (mi * 4 + nj) * 4;
            const int row = m0 + wm + mi * 16 + g;
            const int col = n0 + wn + nj * 8 + 2 * t;   // even
            if (TILED_C) {
                uint32_t* Cw = reinterpret_cast<uint32_t*>(C);
                const int w = (col & 31) >> 1;
                #pragma unroll
                for (int h = 0; h < 2; h++) {
                    const int rr = row + 8 * h;
                    const long toff = ((long)(rr >> 7) * (N >> 5) + (col >> 5)) * TILE_WORDS
                                    + (rr & 127) * 16 + (w ^ ((rr & 7) << 1));
                    uint32_t hw, lw;
                    split2(d[2 * h], d[2 * h + 1], hw, lw);
                    Cw[toff]        = hw;
                    Cw[toff + 2048] = lw;
                }
            } else {
                *reinterpret_cast<float2*>(C + (long)row * N + col)       = make_float2(d[0], d[1]);
                *reinterpret_cast<float2*>(C + (long)(row + 8) * N + col) = make_float2(d[2], d[3]);
            }
        }
    }
}

// ---------------- retile+split: [rows,C] fp32 row-major -> fp16 hi/lo tiles ----------------
__global__ __launch_bounds__(256) void retile(const float* __restrict__ in,
                                              uint32_t* __restrict__ out, int C)
{
    const int rb = blockIdx.y, kb = blockIdx.x;
    uint32_t* otile = out + ((long)rb * (C >> 5) + kb) * TILE_WORDS;
    #pragma unroll
    for (int i = 0; i < 2; i++) {
        const int id = threadIdx.x + 256 * i;   // 0..511, 8 elems each
        const int r  = id >> 2;                 // 0..127
        const int c8 = (id & 3) << 3;           // 0,8,16,24
        const float* src = in + (long)(rb * 128 + r) * C + kb * 32 + c8;
        float4 v0 = *reinterpret_cast<const float4*>(src);
        float4 v1 = *reinterpret_cast<const float4*>(src + 4);
        uint32_t hw[4], lw[4];
        split2(v0.x, v0.y, hw[0], lw[0]);
        split2(v0.z, v0.w, hw[1], lw[1]);
        split2(v1.x, v1.y, hw[2], lw[2]);
        split2(v1.z, v1.w, hw[3], lw[3]);
        const int s   = (r & 7) << 1;
        const int grp = (c8 >> 1) ^ (s & 12);   // aligned-4 word group
        uint32_t* ph = otile + r * 16 + grp;
        uint4 hv, lv;
        if (s & 2) {
            hv = make_uint4(hw[2], hw[3], hw[0], hw[1]);
            lv = make_uint4(lw[2], lw[3], lw[0], lw[1]);
        } else {
            hv = make_uint4(hw[0], hw[1], hw[2], hw[3]);
            lv = make_uint4(lw[0], lw[1], lw[2], lw[3]);
        }
        *reinterpret_cast<uint4*>(ph)        = hv;
        *reinterpret_cast<uint4*>(ph + 2048) = lv;
    }
}

// ---------------- transpose+tile+split: in[R,C] fp32 -> fp16 hi/lo tiles of in^T ----------------
__global__ __launch_bounds__(256) void transpose_tile(
    const float* __restrict__ in, uint32_t* __restrict__ out,
    int R, int C, long sIn, long sOut)
{
    __shared__ float tb[32][33];
    const float* ip = in + (long)blockIdx.z * sIn;
    uint32_t* op = out + (long)blockIdx.z * sOut;
    const int k0 = blockIdx.x * 32;   // K dim (rows of in)
    const int n0 = blockIdx.y * 32;   // N dim (cols of in)
    const int tx = threadIdx.x & 31;
    const int ty = threadIdx.x >> 5;  // 0..7

    #pragma unroll
    for (int i = 0; i < 4; i++)
        tb[ty + 8 * i][tx] = ip[(long)(k0 + ty + 8 * i) * C + n0 + tx];   // tb[k][n]
    __syncthreads();

    const int r  = threadIdx.x >> 3;        // 0..31 output row (n local)
    const int wq = threadIdx.x & 7;         // word pair index
    const int rt = (n0 & 127) + r;
    const int s  = (rt & 7) << 1;
    uint32_t* otile = op + ((long)(n0 >> 7) * (R >> 5) + (k0 >> 5)) * TILE_WORDS;

    uint32_t hw[2], lw[2];
    #pragma unroll
    for (int j = 0; j < 2; j++) {
        const int w = 2 * wq + j;
        split2(tb[2 * w][r], tb[2 * w + 1][r], hw[j], lw[j]);
    }
    uint32_t* ph = otile + rt * 16 + ((2 * wq) ^ s);   // s bit0=0 -> pair stays contiguous
    *reinterpret_cast<uint2*>(ph)        = make_uint2(hw[0], hw[1]);
    *reinterpret_cast<uint2*>(ph + 2048) = make_uint2(lw[0], lw[1]);
}

// ---------------- softmax over 2048 cols, in place + fp16 hi/lo tiled copy ----------------
__inline__ __device__ float warpMax(float v) {
    #pragma unroll
    for (int o = 16; o > 0; o >>= 1) v = fmaxf(v, __shfl_xor_sync(0xffffffffu, v, o));
    return v;
}
__inline__ __device__ float warpSum(float v) {
    #pragma unroll
    for (int o = 16; o > 0; o >>= 1) v += __shfl_xor_sync(0xffffffffu, v, o);
    return v;
}

__global__ __launch_bounds__(256) void softmax2048_dual(
    float* __restrict__ S, uint32_t* __restrict__ Wt)
{
    __shared__ float red[8];
    const int b = blockIdx.x >> 11;
    const int q = blockIdx.x & 2047;
    float4* b4 = reinterpret_cast<float4*>(S + (long)blockIdx.x * 2048);

    float4 v0 = b4[threadIdx.x];
    float4 v1 = b4[threadIdx.x + 256];

    float m = fmaxf(fmaxf(fmaxf(v0.x, v0.y), fmaxf(v0.z, v0.w)),
                    fmaxf(fmaxf(v1.x, v1.y), fmaxf(v1.z, v1.w)));
    m = warpMax(m);
    const int wid = threadIdx.x >> 5, lid = threadIdx.x & 31;
    if (lid == 0) red[wid] = m;
    __syncthreads();
    float bm = red[0];
    #pragma unroll
    for (int i = 1; i < 8; i++) bm = fmaxf(bm, red[i]);
    __syncthreads();

    v0.x = __expf(v0.x - bm); v0.y = __expf(v0.y - bm);
    v0.z = __expf(v0.z - bm); v0.w = __expf(v0.w - bm);
    v1.x = __expf(v1.x - bm); v1.y = __expf(v1.y - bm);
    v1.z = __expf(v1.z - bm); v1.w = __expf(v1.w - bm);

    float s = (v0.x + v0.y) + (v0.z + v0.w) + (v1.x + v1.y) + (v1.z + v1.w);
    s = warpSum(s);
    if (lid == 0) red[wid] = s;
    __syncthreads();
    float bs = 0.f;
    #pragma unroll
    for (int i = 0; i < 8; i++) bs += red[i];
    const float inv = 1.0f / bs;

    v0.x *= inv; v0.y *= inv; v0.z *= inv; v0.w *= inv;
    v1.x *= inv; v1.y *= inv; v1.z *= inv; v1.w *= inv;
    b4[threadIdx.x]       = v0;
    b4[threadIdx.x + 256] = v1;

    // fp16 hi/lo tiled copy
    uint32_t* base = Wt + (long)b * LQ_ * LK_
                   + ((long)(q >> 7) * (LK_ >> 5)) * TILE_WORDS
                   + (q & 127) * 16;
    const int swz = (q & 7) << 1;
    #pragma unroll
    for (int h = 0; h < 2; h++) {
        const int c = threadIdx.x * 4 + h * 1024;
        const float4 v = h ? v1 : v0;
        uint32_t h0, l0, h1, l1;
        split2(v.x, v.y, h0, l0);
        split2(v.z, v.w, h1, l1);
        uint32_t* p = base + ((long)(c >> 5)) * TILE_WORDS + (((c & 31) >> 1) ^ swz);
        *reinterpret_cast<uint2*>(p)        = make_uint2(h0, h1);
        *reinterpret_cast<uint2*>(p + 2048) = make_uint2(l0, l1);
    }
}

// ---------------- launch ----------------
extern "C" void kernel_launch(void* const* d_in, const int* in_sizes, int n_in,
                              void* d_out, int out_size)
{
    const float* key   = (const float*)d_in[0];
    const float* query = (const float*)d_in[1];
    const float* value = (const float*)d_in[2];
    const float* W     = (const float*)d_in[3];
    // bias (d_in[4]): scalar added to every score -> softmax-invariant -> unused.

    float* weights = (float*)d_out;                   // [B, LQ, LK]
    float* ctx     = weights + (long)B_ * LQ_ * LK_;  // [B, LQ, DV]

    uint32_t *qT, *kT, *WtT, *vTT, *qWT, *wT;
    cudaGetSymbolAddress((void**)&qT,  g_qT);
    cudaGetSymbolAddress((void**)&kT,  g_kT);
    cudaGetSymbolAddress((void**)&WtT, g_WtT);
    cudaGetSymbolAddress((void**)&vTT, g_vTT);
    cudaGetSymbolAddress((void**)&qWT, g_qWT);
    cudaGetSymbolAddress((void**)&wT,  g_wT);

    cudaFuncSetAttribute(gemm3x_f16<true>,  cudaFuncAttributeMaxDynamicSharedMemorySize, GEMM_SMEM);
    cudaFuncSetAttribute(gemm3x_f16<false>, cudaFuncAttributeMaxDynamicSharedMemorySize, GEMM_SMEM);

    // pre-tiling (+ fp16 hi/lo split)
    retile<<<dim3(D_ / 32, (B_ * LQ_) / 128), 256>>>(query, qT, D_);
    retile<<<dim3(D_ / 32, (B_ * LK_) / 128), 256>>>(key,   kT, D_);
    transpose_tile<<<dim3(D_ / 32, D_ / 32, 1), 256>>>(W, WtT, D_, D_, 0, 0);
    transpose_tile<<<dim3(LK_ / 32, DV_ / 32, B_), 256>>>(
        value, vTT, LK_, DV_, (long)LK_ * DV_, (long)DV_ * LK_);

    // 1) qW = query @ W : output fp16 hi/lo tiled
    gemm3x_f16<true><<<dim3(D_ / 128, (B_ * LQ_) / 128, 1), 256, GEMM_SMEM>>>(
        qT, WtT, (float*)qWT, B_ * LQ_, D_, D_, 0, 0, 0);

    // 2) scores = qW @ key^T (per batch) -> d_out weights region (row-major fp32)
    gemm3x_f16<false><<<dim3(LK_ / 128, LQ_ / 128, B_), 256, GEMM_SMEM>>>(
        qWT, kT, weights, LQ_, LK_, D_,
        (long)LQ_ * D_, (long)LK_ * D_, (long)LQ_ * LK_);

    // 3) softmax in place + fp16 hi/lo tiled copy
    softmax2048_dual<<<B_ * LQ_, 256>>>(weights, wT);

    // 4) ctx = weights @ value (per batch)
    gemm3x_f16<false><<<dim3(DV_ / 128, LQ_ / 128, B_), 256, GEMM_SMEM>>>(
        wT, vTT, ctx, LQ_, DV_, LK_,
        (long)LQ_ * LK_, (long)LK_ * DV_, (long)LQ_ * DV_);
}

// round 17
// speedup vs baseline: 2.5812x; 1.0386x over previous
#include <cuda_runtime.h>
#include <cuda_fp16.h>
#include <cstdint>

#define B_   8
#define LQ_  2048
#define LK_  2048
#define D_   1024
#define DV_  1024

// ---------------- tiled scratch (device globals) ----------------
// Tile = 16KB = [hi plane: 128 rows x 16 half2 words][lo plane: same].
// Element (r,c): half in word w=c>>1 (low half = even c), stored at
// word offset r*16 + (w ^ ((r&6)<<1)); lo plane at +2048 words.
// Swizzle flips word bits 2-3 only -> 16B ldmatrix rows stay contiguous,
// and each ldmatrix phase (8 rows, 8-aligned) is bank-conflict-free.
__device__ uint32_t g_qT [(long)B_ * LQ_ * D_];    // query tiled (A of G1)
__device__ uint32_t g_kT [(long)B_ * LK_ * D_];    // key tiled (B of G2)
__device__ uint32_t g_WtT[(long)D_ * D_];          // W^T tiled (B of G1)
__device__ uint32_t g_vTT[(long)B_ * DV_ * LK_];   // value^T tiled (B of G3)
__device__ uint32_t g_qWT[(long)B_ * LQ_ * D_];    // qW tiled (A of G2)
__device__ uint32_t g_wT [(long)B_ * LQ_ * LK_];   // weights tiled (A of G3)

// ---------------- helpers ----------------
__device__ __forceinline__ uint32_t smem_u32(const void* p) {
    uint32_t a;
    asm("{ .reg .u64 t; cvta.to.shared.u64 t, %1; cvt.u32.u64 %0, t; }" : "=r"(a) : "l"(p));
    return a;
}

// split two fp32 -> packed f16 hi word + f16 lo word (lo = x - f32(hi))
__device__ __forceinline__ void split2(float x0, float x1, uint32_t& hw, uint32_t& lw) {
    __half2 h = __floats2half2_rn(x0, x1);           // .x (low) = x0
    float2 hf = __half22float2(h);
    __half2 l = __floats2half2_rn(x0 - hf.x, x1 - hf.y);
    hw = *reinterpret_cast<uint32_t*>(&h);
    lw = *reinterpret_cast<uint32_t*>(&l);
}

__device__ __forceinline__ void mma_f16(float* d, const uint32_t* a, const uint32_t* b) {
    asm volatile(
        "mma.sync.aligned.m16n8k16.row.col.f32.f16.f16.f32 "
        "{%0,%1,%2,%3}, {%4,%5,%6,%7}, {%8,%9}, {%0,%1,%2,%3};"
        : "+f"(d[0]), "+f"(d[1]), "+f"(d[2]), "+f"(d[3])
        : "r"(a[0]), "r"(a[1]), "r"(a[2]), "r"(a[3]),
          "r"(b[0]), "r"(b[1]));
}

__device__ __forceinline__ void ldsm_x4(uint32_t* r, uint32_t addr) {
    asm volatile("ldmatrix.sync.aligned.m8n8.x4.shared.b16 {%0,%1,%2,%3}, [%4];"
                 : "=r"(r[0]), "=r"(r[1]), "=r"(r[2]), "=r"(r[3]) : "r"(addr));
}

__device__ __forceinline__ void bulk_cp(uint32_t dst, const void* src,
                                        uint32_t bytes, uint32_t mbar) {
    asm volatile("cp.async.bulk.shared::cluster.global.mbarrier::complete_tx::bytes "
                 "[%0], [%1], %2, [%3];"
                 :: "r"(dst), "l"(src), "r"(bytes), "r"(mbar) : "memory");
}

#define MBARRIER_INIT(m, c) \
    asm volatile("mbarrier.init.shared.b64 [%0], %1;" :: "r"(m), "r"(c) : "memory")
#define MBARRIER_EXPECT_TX(m, b) \
    asm volatile("mbarrier.arrive.expect_tx.shared.b64 _, [%0], %1;" :: "r"(m), "r"(b) : "memory")

#define MBARRIER_WAIT_PARITY(mbar_smem_addr, phase_parity) do { \
    uint32_t _mbar = (uint32_t)(mbar_smem_addr); \
    uint32_t _parity = (uint32_t)(phase_parity); \
    uint32_t _done; \
    asm volatile( \
        "{\n\t.reg .pred p;\n\t" \
        "mbarrier.try_wait.parity.acquire.cta.shared::cta.b64 p, [%1], %2;\n\t" \
        "selp.b32 %0, 1, 0, p;\n\t}" \
        : "=r"(_done) : "r"(_mbar), "r"(_parity) : "memory"); \
    if (!_done) { \
        asm volatile( \
            "{\n\t.reg .pred P1;\n\t" \
            "WAIT_LOOP_%=:\n\t" \
            "mbarrier.try_wait.parity.acquire.cta.shared::cta.b64 P1, [%0], %1, 0x989680;\n\t" \
            "@P1 bra.uni WAIT_DONE_%=;\n\t" \
            "bra.uni WAIT_LOOP_%=;\n\t" \
            "WAIT_DONE_%=:\n\t}" \
            :: "r"(_mbar), "r"(_parity) : "memory"); \
    } \
} while (0)

// ---------------- GEMM config ----------------
#define STAGES 3
#define TILE_WORDS 4096                  // 16KB: hi 2048 + lo 2048
#define TILE_BYTES  16384
#define STAGE_BYTES (2 * TILE_BYTES)     // A tile + B tile
#define SMEM_BASE   1024
#define GEMM_SMEM   (SMEM_BASE + STAGES * STAGE_BYTES)   // 99328 -> 2 CTAs/SM

// C[M,N] = A[M,K] @ Bt[N,K]^T. A, Bt pre-split fp16 hi/lo tiled (above).
// 3xFP16 emulation: D += Ahi*Bhi + Ahi*Blo + Alo*Bhi (fp32 accum).
// 256 thr, 8 warps 2x4, 64x32 warp tiles; fragments via ldmatrix.x4.
template<bool TILED_C>
__global__ __launch_bounds__(256, 2) void gemm3x_f16(
    const uint32_t* __restrict__ A, const uint32_t* __restrict__ Bt, float* __restrict__ C,
    int M, int N, int K, long sA, long sB, long sC)
{
    extern __shared__ float sf[];
    const uint32_t sbase = smem_u32(sf);

    A  += (long)blockIdx.z * sA;
    Bt += (long)blockIdx.z * sB;
    C  += (long)blockIdx.z * sC;

    const int tid  = threadIdx.x;
    const int lane = tid & 31;
    const int warp = tid >> 5;
    const int g    = lane >> 2;          // 0..7
    const int t    = lane & 3;           // 0..3
    const int wm   = (warp >> 2) * 64;   // warp M offset (0/64)
    const int wn   = (warp & 3) * 32;    // warp N offset (0/32/64/96)
    const int Kb   = K >> 5;

    // ldmatrix per-lane byte offsets (within a plane)
    const int rq = lane & 7;
    const int qq = lane >> 3;            // quadrant 0..3
    uint32_t aoff[4], boff[2];
    #pragma unroll
    for (int mi = 0; mi < 4; mi++) {
        const int row = wm + mi * 16 + ((qq & 1) << 3) + rq;
        const int w   = ((qq >> 1) << 2) ^ ((row & 6) << 1);
        aoff[mi] = (uint32_t)(row * 16 + w) * 4u;
    }
    #pragma unroll
    for (int p = 0; p < 2; p++) {
        const int row = wn + (((p << 1) + (qq >> 1)) << 3) + rq;
        const int w   = ((qq & 1) << 2) ^ ((row & 6) << 1);
        boff[p] = (uint32_t)(row * 16 + w) * 4u;
    }

    if (tid == 0) {
        #pragma unroll
        for (int s = 0; s < STAGES; s++) MBARRIER_INIT(sbase + 8 * s, 1);
    }
    __syncthreads();

    auto fill = [&](int it2) {
        if (tid == 0) {
            const int buf = it2 % STAGES;
            const uint32_t mbar = sbase + 8 * buf;
            const uint32_t st   = sbase + SMEM_BASE + buf * STAGE_BYTES;
            MBARRIER_EXPECT_TX(mbar, STAGE_BYTES);
            bulk_cp(st,              A  + ((long)blockIdx.y * Kb + it2) * TILE_WORDS,
                    TILE_BYTES, mbar);
            bulk_cp(st + TILE_BYTES, Bt + ((long)blockIdx.x * Kb + it2) * TILE_WORDS,
                    TILE_BYTES, mbar);
        }
    };

    float acc[64];
    #pragma unroll
    for (int i = 0; i < 64; i++) acc[i] = 0.0f;

    fill(0); fill(1);

    for (int it = 0; it < Kb; it++) {
        const int buf = it % STAGES;
        if (it + 2 < Kb) fill(it + 2);   // buf (it-1)%3: reads done (sync below)
        MBARRIER_WAIT_PARITY(sbase + 8 * buf, (it / STAGES) & 1);

        const uint32_t Ah_base = sbase + SMEM_BASE + buf * STAGE_BYTES;  // A hi
        const uint32_t Al_base = Ah_base + 8192;                         // A lo
        const uint32_t Bh_base = Ah_base + 16384;                        // B hi
        const uint32_t Bl_base = Ah_base + 24576;                        // B lo

        #pragma unroll
        for (int kk = 0; kk < 2; kk++) {     // two K=16 steps per 32-K tile
            const uint32_t kx = (uint32_t)kk << 5;   // ^32B = flip word bit3
            uint32_t ah[16], al[16], bh[8], bl[8];
            #pragma unroll
            for (int mi = 0; mi < 4; mi++) {
                ldsm_x4(&ah[mi * 4], (Ah_base + aoff[mi]) ^ kx);
                ldsm_x4(&al[mi * 4], (Al_base + aoff[mi]) ^ kx);
            }
            #pragma unroll
            for (int p = 0; p < 2; p++) {
                ldsm_x4(&bh[p * 4], (Bh_base + boff[p]) ^ kx);
                ldsm_x4(&bl[p * 4], (Bl_base + boff[p]) ^ kx);
            }
            #pragma unroll
            for (int mi = 0; mi < 4; mi++)
                #pragma unroll
                for (int nj = 0; nj < 4; nj++) {
                    float* d = acc + (mi * 4 + nj) * 4;
                    mma_f16(d, &ah[mi * 4], &bh[nj * 2]);   // hi*hi
                    mma_f16(d, &ah[mi * 4], &bl[nj * 2]);   // hi*lo
                    mma_f16(d, &al[mi * 4], &bh[nj * 2]);   // lo*hi
                }
        }
        __syncthreads();
    }

    // ---- epilogue ----
    const int m0 = blockIdx.y * 128;
    const int n0 = blockIdx.x * 128;
    #pragma unroll
    for (int mi = 0; mi < 4; mi++) {
        #pragma unroll
        for (int nj = 0; nj < 4; nj++) {
            const float* d = acc + (mi * 4 + nj) * 4;
            const int row = m0 + wm + mi * 16 + g;
            const int col = n0 + wn + nj * 8 + 2 * t;   // even
            if (TILED_C) {
                uint32_t* Cw = reinterpret_cast<uint32_t*>(C);
                const int w = (col & 31) >> 1;
                #pragma unroll
                for (int h = 0; h < 2; h++) {
                    const int rr = row + 8 * h;
                    const long toff = ((long)(rr >> 7) * (N >> 5) + (col >> 5)) * TILE_WORDS
                                    + (rr & 127) * 16 + (w ^ ((rr & 6) << 1));
                    uint32_t hw, lw;
                    split2(d[2 * h], d[2 * h + 1], hw, lw);
                    Cw[toff]        = hw;
                    Cw[toff + 2048] = lw;
                }
            } else {
                *reinterpret_cast<float2*>(C + (long)row * N + col)       = make_float2(d[0], d[1]);
                *reinterpret_cast<float2*>(C + (long)(row + 8) * N + col) = make_float2(d[2], d[3]);
            }
        }
    }
}

// ---------------- retile+split: [rows,C] fp32 row-major -> fp16 hi/lo tiles ----------------
__global__ __launch_bounds__(256) void retile(const float* __restrict__ in,
                                              uint32_t* __restrict__ out, int C)
{
    const int rb = blockIdx.y, kb = blockIdx.x;
    uint32_t* otile = out + ((long)rb * (C >> 5) + kb) * TILE_WORDS;
    #pragma unroll
    for (int i = 0; i < 2; i++) {
        const int id = threadIdx.x + 256 * i;   // 0..511, 8 elems each
        const int r  = id >> 2;                 // 0..127
        const int c8 = (id & 3) << 3;           // 0,8,16,24
        const float* src = in + (long)(rb * 128 + r) * C + kb * 32 + c8;
        float4 v0 = *reinterpret_cast<const float4*>(src);
        float4 v1 = *reinterpret_cast<const float4*>(src + 4);
        uint32_t hw[4], lw[4];
        split2(v0.x, v0.y, hw[0], lw[0]);
        split2(v0.z, v0.w, hw[1], lw[1]);
        split2(v1.x, v1.y, hw[2], lw[2]);
        split2(v1.z, v1.w, hw[3], lw[3]);
        const int grp = (c8 >> 1) ^ ((r & 6) << 1);   // 4-word aligned group
        uint32_t* ph = otile + r * 16 + grp;
        *reinterpret_cast<uint4*>(ph)        = make_uint4(hw[0], hw[1], hw[2], hw[3]);
        *reinterpret_cast<uint4*>(ph + 2048) = make_uint4(lw[0], lw[1], lw[2], lw[3]);
    }
}

// ---------------- transpose+tile+split: in[R,C] fp32 -> fp16 hi/lo tiles of in^T ----------------
__global__ __launch_bounds__(256) void transpose_tile(
    const float* __restrict__ in, uint32_t* __restrict__ out,
    int R, int C, long sIn, long sOut)
{
    __shared__ float tb[32][33];
    const float* ip = in + (long)blockIdx.z * sIn;
    uint32_t* op = out + (long)blockIdx.z * sOut;
    const int k0 = blockIdx.x * 32;   // K dim (rows of in)
    const int n0 = blockIdx.y * 32;   // N dim (cols of in)
    const int tx = threadIdx.x & 31;
    const int ty = threadIdx.x >> 5;  // 0..7

    #pragma unroll
    for (int i = 0; i < 4; i++)
        tb[ty + 8 * i][tx] = ip[(long)(k0 + ty + 8 * i) * C + n0 + tx];   // tb[k][n]
    __syncthreads();

    const int r  = threadIdx.x >> 3;        // 0..31 output row (n local)
    const int wq = threadIdx.x & 7;         // word pair index
    const int rt = (n0 & 127) + r;
    const int s  = (rt & 6) << 1;
    uint32_t* otile = op + ((long)(n0 >> 7) * (R >> 5) + (k0 >> 5)) * TILE_WORDS;

    uint32_t hw[2], lw[2];
    #pragma unroll
    for (int j = 0; j < 2; j++) {
        const int w = 2 * wq + j;
        split2(tb[2 * w][r], tb[2 * w + 1][r], hw[j], lw[j]);
    }
    uint32_t* ph = otile + rt * 16 + ((2 * wq) ^ s);   // s flips bits 2-3 only
    *reinterpret_cast<uint2*>(ph)        = make_uint2(hw[0], hw[1]);
    *reinterpret_cast<uint2*>(ph + 2048) = make_uint2(lw[0], lw[1]);
}

// ---------------- softmax over 2048 cols, in place + fp16 hi/lo tiled copy ----------------
__inline__ __device__ float warpMax(float v) {
    #pragma unroll
    for (int o = 16; o > 0; o >>= 1) v = fmaxf(v, __shfl_xor_sync(0xffffffffu, v, o));
    return v;
}
__inline__ __device__ float warpSum(float v) {
    #pragma unroll
    for (int o = 16; o > 0; o >>= 1) v += __shfl_xor_sync(0xffffffffu, v, o);
    return v;
}

__global__ __launch_bounds__(256) void softmax2048_dual(
    float* __restrict__ S, uint32_t* __restrict__ Wt)
{
    __shared__ float red[8];
    const int b = blockIdx.x >> 11;
    const int q = blockIdx.x & 2047;
    float4* b4 = reinterpret_cast<float4*>(S + (long)blockIdx.x * 2048);

    float4 v0 = b4[threadIdx.x];
    float4 v1 = b4[threadIdx.x + 256];

    float m = fmaxf(fmaxf(fmaxf(v0.x, v0.y), fmaxf(v0.z, v0.w)),
                    fmaxf(fmaxf(v1.x, v1.y), fmaxf(v1.z, v1.w)));
    m = warpMax(m);
    const int wid = threadIdx.x >> 5, lid = threadIdx.x & 31;
    if (lid == 0) red[wid] = m;
    __syncthreads();
    float bm = red[0];
    #pragma unroll
    for (int i = 1; i < 8; i++) bm = fmaxf(bm, red[i]);
    __syncthreads();

    v0.x = __expf(v0.x - bm); v0.y = __expf(v0.y - bm);
    v0.z = __expf(v0.z - bm); v0.w = __expf(v0.w - bm);
    v1.x = __expf(v1.x - bm); v1.y = __expf(v1.y - bm);
    v1.z = __expf(v1.z - bm); v1.w = __expf(v1.w - bm);

    float s = (v0.x + v0.y) + (v0.z + v0.w) + (v1.x + v1.y) + (v1.z + v1.w);
    s = warpSum(s);
    if (lid == 0) red[wid] = s;
    __syncthreads();
    float bs = 0.f;
    #pragma unroll
    for (int i = 0; i < 8; i++) bs += red[i];
    const float inv = 1.0f / bs;

    v0.x *= inv; v0.y *= inv; v0.z *= inv; v0.w *= inv;
    v1.x *= inv; v1.y *= inv; v1.z *= inv; v1.w *= inv;
    b4[threadIdx.x]       = v0;
    b4[threadIdx.x + 256] = v1;

    // fp16 hi/lo tiled copy
    uint32_t* base = Wt + (long)b * LQ_ * LK_
                   + ((long)(q >> 7) * (LK_ >> 5)) * TILE_WORDS
                   + (q & 127) * 16;
    const int swz = (q & 6) << 1;
    #pragma unroll
    for (int h = 0; h < 2; h++) {
        const int c = threadIdx.x * 4 + h * 1024;
        const float4 v = h ? v1 : v0;
        uint32_t h0, l0, h1, l1;
        split2(v.x, v.y, h0, l0);
        split2(v.z, v.w, h1, l1);
        uint32_t* p = base + ((long)(c >> 5)) * TILE_WORDS + (((c & 31) >> 1) ^ swz);
        *reinterpret_cast<uint2*>(p)        = make_uint2(h0, h1);
        *reinterpret_cast<uint2*>(p + 2048) = make_uint2(l0, l1);
    }
}

// ---------------- launch ----------------
extern "C" void kernel_launch(void* const* d_in, const int* in_sizes, int n_in,
                              void* d_out, int out_size)
{
    const float* key   = (const float*)d_in[0];
    const float* query = (const float*)d_in[1];
    const float* value = (const float*)d_in[2];
    const float* W     = (const float*)d_in[3];
    // bias (d_in[4]): scalar added to every score -> softmax-invariant -> unused.

    float* weights = (float*)d_out;                   // [B, LQ, LK]
    float* ctx     = weights + (long)B_ * LQ_ * LK_;  // [B, LQ, DV]

    uint32_t *qT, *kT, *WtT, *vTT, *qWT, *wT;
    cudaGetSymbolAddress((void**)&qT,  g_qT);
    cudaGetSymbolAddress((void**)&kT,  g_kT);
    cudaGetSymbolAddress((void**)&WtT, g_WtT);
    cudaGetSymbolAddress((void**)&vTT, g_vTT);
    cudaGetSymbolAddress((void**)&qWT, g_qWT);
    cudaGetSymbolAddress((void**)&wT,  g_wT);

    cudaFuncSetAttribute(gemm3x_f16<true>,  cudaFuncAttributeMaxDynamicSharedMemorySize, GEMM_SMEM);
    cudaFuncSetAttribute(gemm3x_f16<false>, cudaFuncAttributeMaxDynamicSharedMemorySize, GEMM_SMEM);

    // pre-tiling (+ fp16 hi/lo split)
    retile<<<dim3(D_ / 32, (B_ * LQ_) / 128), 256>>>(query, qT, D_);
    retile<<<dim3(D_ / 32, (B_ * LK_) / 128), 256>>>(key,   kT, D_);
    transpose_tile<<<dim3(D_ / 32, D_ / 32, 1), 256>>>(W, WtT, D_, D_, 0, 0);
    transpose_tile<<<dim3(LK_ / 32, DV_ / 32, B_), 256>>>(
        value, vTT, LK_, DV_, (long)LK_ * DV_, (long)DV_ * LK_);

    // 1) qW = query @ W : output fp16 hi/lo tiled
    gemm3x_f16<true><<<dim3(D_ / 128, (B_ * LQ_) / 128, 1), 256, GEMM_SMEM>>>(
        qT, WtT, (float*)qWT, B_ * LQ_, D_, D_, 0, 0, 0);

    // 2) scores = qW @ key^T (per batch) -> d_out weights region (row-major fp32)
    gemm3x_f16<false><<<dim3(LK_ / 128, LQ_ / 128, B_), 256, GEMM_SMEM>>>(
        qWT, kT, weights, LQ_, LK_, D_,
        (long)LQ_ * D_, (long)LK_ * D_, (long)LQ_ * LK_);

    // 3) softmax in place + fp16 hi/lo tiled copy
    softmax2048_dual<<<B_ * LQ_, 256>>>(weights, wT);

    // 4) ctx = weights @ value (per batch)
    gemm3x_f16<false><<<dim3(DV_ / 128, LQ_ / 128, B_), 256, GEMM_SMEM>>>(
        wT, vTT, ctx, LQ_, DV_, LK_,
        (long)LQ_ * LK_, (long)LK_ * DV_, (long)LQ_ * DV_);
}